// round 5
// baseline (speedup 1.0000x reference)
#include <cuda_runtime.h>
#include <cuda_fp16.h>
#include <cstdint>

#define DZ 1024
#define DM 4096
#define NROWS 16384
#define LN_EPS 1e-5f
#define CLAMPV 3.0f

// -------- scratch (static device arrays; no allocation) --------
__device__ __align__(16) __half g_A16[NROWS * DZ];   // 32 MB, [M,K] row-major fp16
__device__ __align__(16) __half g_W16[DZ * DM];      //  8 MB, [K,N] row-major fp16

// ======================= small helpers =======================
__device__ __forceinline__ uint32_t smem_u32(const void* p) {
    uint32_t a;
    asm("{ .reg .u64 t; cvta.to.shared.u64 t, %1; cvt.u32.u64 %0, t; }"
        : "=r"(a) : "l"(p));
    return a;
}

__device__ __forceinline__ void cp_async16(uint32_t dst, const void* src) {
    asm volatile("cp.async.cg.shared.global [%0], [%1], 16;"
                 :: "r"(dst), "l"(src));
}
__device__ __forceinline__ void cp_commit() {
    asm volatile("cp.async.commit_group;");
}
template <int N>
__device__ __forceinline__ void cp_wait() {
    asm volatile("cp.async.wait_group %0;" :: "n"(N));
}

__device__ __forceinline__ void ldsm_x4(uint32_t& r0, uint32_t& r1, uint32_t& r2,
                                        uint32_t& r3, uint32_t addr) {
    asm volatile("ldmatrix.sync.aligned.m8n8.x4.shared.b16 {%0,%1,%2,%3}, [%4];"
                 : "=r"(r0), "=r"(r1), "=r"(r2), "=r"(r3) : "r"(addr));
}
__device__ __forceinline__ void ldsm_x4_t(uint32_t& r0, uint32_t& r1, uint32_t& r2,
                                          uint32_t& r3, uint32_t addr) {
    asm volatile("ldmatrix.sync.aligned.m8n8.x4.trans.shared.b16 {%0,%1,%2,%3}, [%4];"
                 : "=r"(r0), "=r"(r1), "=r"(r2), "=r"(r3) : "r"(addr));
}

__device__ __forceinline__ void mma16816(float* c, const uint32_t* a,
                                         uint32_t b0, uint32_t b1) {
    asm volatile(
        "mma.sync.aligned.m16n8k16.row.col.f32.f16.f16.f32 "
        "{%0,%1,%2,%3},{%4,%5,%6,%7},{%8,%9},{%0,%1,%2,%3};"
        : "+f"(c[0]), "+f"(c[1]), "+f"(c[2]), "+f"(c[3])
        : "r"(a[0]), "r"(a[1]), "r"(a[2]), "r"(a[3]), "r"(b0), "r"(b1));
}

// ======================= Kernel 1: LayerNorm -> fp16 A =======================
__global__ __launch_bounds__(128) void ln_fp16_kernel(
    const float* __restrict__ z, const float* __restrict__ gamma,
    const float* __restrict__ beta)
{
    const int row = blockIdx.x;
    const int tid = threadIdx.x;
    const float4* zr = reinterpret_cast<const float4*>(z + (size_t)row * DZ);
    float4 a0 = zr[tid * 2], a1 = zr[tid * 2 + 1];
    float v[8] = {a0.x, a0.y, a0.z, a0.w, a1.x, a1.y, a1.z, a1.w};

    float s = 0.f, sq = 0.f;
#pragma unroll
    for (int i = 0; i < 8; i++) { s += v[i]; sq += v[i] * v[i]; }
#pragma unroll
    for (int o = 16; o > 0; o >>= 1) {
        s  += __shfl_xor_sync(0xFFFFFFFFu, s, o);
        sq += __shfl_xor_sync(0xFFFFFFFFu, sq, o);
    }
    __shared__ float ss[4], ssq[4], bc[2];
    const int wid = tid >> 5, lid = tid & 31;
    if (lid == 0) { ss[wid] = s; ssq[wid] = sq; }
    __syncthreads();
    if (tid == 0) {
        float ts = ss[0] + ss[1] + ss[2] + ss[3];
        float tq = ssq[0] + ssq[1] + ssq[2] + ssq[3];
        float mu = ts * (1.0f / DZ);
        float var = tq * (1.0f / DZ) - mu * mu;
        bc[0] = mu;
        bc[1] = rsqrtf(var + LN_EPS);
    }
    __syncthreads();
    const float mu = bc[0], inv = bc[1];

    const float4* gp = reinterpret_cast<const float4*>(gamma);
    const float4* bp = reinterpret_cast<const float4*>(beta);
    float4 g0 = gp[tid * 2], g1 = gp[tid * 2 + 1];
    float4 b0 = bp[tid * 2], b1 = bp[tid * 2 + 1];
    float gv[8] = {g0.x, g0.y, g0.z, g0.w, g1.x, g1.y, g1.z, g1.w};
    float bv[8] = {b0.x, b0.y, b0.z, b0.w, b1.x, b1.y, b1.z, b1.w};

    __half h[8];
#pragma unroll
    for (int i = 0; i < 8; i++)
        h[i] = __float2half((v[i] - mu) * inv * gv[i] + bv[i]);
    *reinterpret_cast<uint4*>(&g_A16[(size_t)row * DZ + tid * 8]) =
        *reinterpret_cast<uint4*>(h);
}

// ======================= Kernel 2: W -> fp16 =======================
__global__ __launch_bounds__(256) void w_fp16_kernel(const float* __restrict__ W)
{
    const size_t i0 = ((size_t)blockIdx.x * 256 + threadIdx.x) * 8;
    const float4* src = reinterpret_cast<const float4*>(W + i0);
    float4 a = src[0], b = src[1];
    __half h[8] = {__float2half(a.x), __float2half(a.y), __float2half(a.z), __float2half(a.w),
                   __float2half(b.x), __float2half(b.y), __float2half(b.z), __float2half(b.w)};
    *reinterpret_cast<uint4*>(&g_W16[i0]) = *reinterpret_cast<uint4*>(h);
}

// ======================= Kernel 3: fp16 HMMA GEMM + epilogue =======================
// CTA tile 256x128, BK=32, 4-stage cp.async pipeline, 8 warps (warp tile 64x64).
#define BM 256
#define BN 128
#define BK 32
#define NSTAGE 4
#define NCHUNK (DZ / BK)          // 32
#define GTHREADS 256

#define SA_STRIDE 40              // halves per A row (pad 8)
#define SB_STRIDE 136             // halves per B row (pad 8)
#define A_STAGE_BYTES (BM * SA_STRIDE * 2)   // 20480
#define B_STAGE_BYTES (BK * SB_STRIDE * 2)   // 8704
#define STAGE_BYTES (A_STAGE_BYTES + B_STAGE_BYTES)   // 29184
#define SMEM_TOTAL (NSTAGE * STAGE_BYTES)             // 116736

__global__ __launch_bounds__(GTHREADS, 1) void gemm_kernel(
    const float* __restrict__ bias, const float* __restrict__ scale,
    float* __restrict__ out)
{
    extern __shared__ char smem[];
    const uint32_t sbase = smem_u32(smem);
    const int tid = threadIdx.x;
    const int wid = tid >> 5;
    const int lane = tid & 31;
    const int bn = blockIdx.x;            // 0..31  (N tiles of 128)  -- fastest for L2 reuse
    const int bm = blockIdx.y;            // 0..63  (M tiles of 256)
    const int wm = wid >> 1;              // 0..3  (64-row band)
    const int wn = wid & 1;               // 0..1  (64-col band)

    const __half* Abase = g_A16 + (size_t)bm * BM * DZ;
    const __half* Wbase = g_W16 + (size_t)bn * BN;

    const int arow = tid >> 2, ach = tid & 3;    // A: 256 rows x 4 x 16B (4 iters of 64 rows)
    const int brow = tid >> 4, bch = tid & 15;   // B: 32 rows x 16 x 16B (2 iters of 16 rows)

    float acc[4][8][4];
#pragma unroll
    for (int i = 0; i < 4; i++)
#pragma unroll
        for (int j = 0; j < 8; j++)
#pragma unroll
            for (int q = 0; q < 4; q++) acc[i][j][q] = 0.f;

    auto load_stage = [&](int c, int st) {
        const int k0 = c * BK;
        const uint32_t sa = sbase + st * STAGE_BYTES;
        const uint32_t sb = sa + A_STAGE_BYTES;
#pragma unroll
        for (int i = 0; i < 4; i++) {
            const int r = arow + i * 64;
            cp_async16(sa + r * (SA_STRIDE * 2) + ach * 16,
                       Abase + (size_t)r * DZ + k0 + ach * 8);
        }
#pragma unroll
        for (int i = 0; i < 2; i++) {
            const int r = brow + i * 16;
            cp_async16(sb + r * (SB_STRIDE * 2) + bch * 16,
                       Wbase + (size_t)(k0 + r) * DM + bch * 8);
        }
        cp_commit();
    };

    load_stage(0, 0);
    load_stage(1, 1);
    load_stage(2, 2);

    for (int c = 0; c < NCHUNK; c++) {
        cp_wait<NSTAGE - 2>();
        __syncthreads();
        if (c + NSTAGE - 1 < NCHUNK) load_stage(c + NSTAGE - 1, (c + NSTAGE - 1) % NSTAGE);

        const int st = c % NSTAGE;
        const uint32_t sa = sbase + st * STAGE_BYTES;
        const uint32_t sb = sa + A_STAGE_BYTES;
#pragma unroll
        for (int kk = 0; kk < 2; kk++) {
            uint32_t af[4][4];
#pragma unroll
            for (int mt = 0; mt < 4; mt++) {
                const int r = wm * 64 + mt * 16 + (lane & 15);
                const int cb = (kk * 16 + (lane >> 4) * 8) * 2;
                ldsm_x4(af[mt][0], af[mt][1], af[mt][2], af[mt][3],
                        sa + r * (SA_STRIDE * 2) + cb);
            }
            uint32_t bf[4][4];
#pragma unroll
            for (int nt = 0; nt < 4; nt++) {
                const int r = kk * 16 + (lane & 15);
                const int cb = (wn * 64 + nt * 16 + (lane >> 4) * 8) * 2;
                ldsm_x4_t(bf[nt][0], bf[nt][1], bf[nt][2], bf[nt][3],
                          sb + r * (SB_STRIDE * 2) + cb);
            }
#pragma unroll
            for (int mt = 0; mt < 4; mt++) {
#pragma unroll
                for (int nt = 0; nt < 4; nt++) {
                    mma16816(acc[mt][nt * 2],     af[mt], bf[nt][0], bf[nt][1]);
                    mma16816(acc[mt][nt * 2 + 1], af[mt], bf[nt][2], bf[nt][3]);
                }
            }
        }
        __syncthreads();
    }

    // ---- epilogue: (acc + bias) * scale -> tanh clamp, direct fp32 stores ----
    const float sc = *scale;
    const int col0 = bn * BN + wn * 64 + (lane & 3) * 2;
    const int row0 = bm * BM + wm * 64 + (lane >> 2);
#pragma unroll
    for (int mt = 0; mt < 4; mt++) {
#pragma unroll
        for (int nt = 0; nt < 8; nt++) {
            const int col = col0 + nt * 8;
            const float b0 = __ldg(bias + col), b1 = __ldg(bias + col + 1);
#pragma unroll
            for (int half = 0; half < 2; half++) {
                const size_t r = (size_t)(row0 + mt * 16 + half * 8);
                float x0 = (acc[mt][nt][half * 2]     + b0) * sc;
                float x1 = (acc[mt][nt][half * 2 + 1] + b1) * sc;
                float2 o;
                o.x = tanhf(x0 * (1.0f / CLAMPV)) * CLAMPV;
                o.y = tanhf(x1 * (1.0f / CLAMPV)) * CLAMPV;
                *reinterpret_cast<float2*>(out + r * DM + col) = o;
            }
        }
    }
}

// ======================= launch =======================
extern "C" void kernel_launch(void* const* d_in, const int* in_sizes, int n_in,
                              void* d_out, int out_size)
{
    (void)in_sizes; (void)n_in; (void)out_size;
    const float* z     = (const float*)d_in[0];
    const float* gamma = (const float*)d_in[1];
    const float* beta  = (const float*)d_in[2];
    const float* W     = (const float*)d_in[3];
    const float* bias  = (const float*)d_in[4];
    const float* scale = (const float*)d_in[5];
    float* out = (float*)d_out;

    ln_fp16_kernel<<<NROWS, 128>>>(z, gamma, beta);
    w_fp16_kernel<<<(DZ * DM) / (256 * 8), 256>>>(W);

    cudaFuncSetAttribute(gemm_kernel, cudaFuncAttributeMaxDynamicSharedMemorySize,
                         SMEM_TOTAL);
    dim3 gg(DM / BN, NROWS / BM);
    gemm_kernel<<<gg, GTHREADS, SMEM_TOTAL>>>(bias, scale, out);
}

// round 6
// speedup vs baseline: 1.0094x; 1.0094x over previous
#include <cuda_runtime.h>
#include <cuda_fp16.h>
#include <cstdint>

#define DZ 1024
#define DM 4096
#define NROWS 16384
#define LN_EPS 1e-5f
#define CLAMPV 3.0f

// -------- scratch (static device arrays; no allocation) --------
__device__ __align__(16) __half g_A16[NROWS * DZ];   // 32 MB, [M,K] row-major fp16
__device__ __align__(16) __half g_W16[DZ * DM];      //  8 MB, [K,N] row-major fp16

// ======================= small helpers =======================
__device__ __forceinline__ uint32_t smem_u32(const void* p) {
    uint32_t a;
    asm("{ .reg .u64 t; cvta.to.shared.u64 t, %1; cvt.u32.u64 %0, t; }"
        : "=r"(a) : "l"(p));
    return a;
}

__device__ __forceinline__ void cp_async16(uint32_t dst, const void* src) {
    asm volatile("cp.async.cg.shared.global [%0], [%1], 16;"
                 :: "r"(dst), "l"(src));
}
__device__ __forceinline__ void cp_commit() {
    asm volatile("cp.async.commit_group;");
}
template <int N>
__device__ __forceinline__ void cp_wait() {
    asm volatile("cp.async.wait_group %0;" :: "n"(N));
}

__device__ __forceinline__ void ldsm_x4(uint32_t& r0, uint32_t& r1, uint32_t& r2,
                                        uint32_t& r3, uint32_t addr) {
    asm volatile("ldmatrix.sync.aligned.m8n8.x4.shared.b16 {%0,%1,%2,%3}, [%4];"
                 : "=r"(r0), "=r"(r1), "=r"(r2), "=r"(r3) : "r"(addr));
}
__device__ __forceinline__ void ldsm_x4_t(uint32_t& r0, uint32_t& r1, uint32_t& r2,
                                          uint32_t& r3, uint32_t addr) {
    asm volatile("ldmatrix.sync.aligned.m8n8.x4.trans.shared.b16 {%0,%1,%2,%3}, [%4];"
                 : "=r"(r0), "=r"(r1), "=r"(r2), "=r"(r3) : "r"(addr));
}

__device__ __forceinline__ void mma16816(float* c, const uint32_t* a,
                                         uint32_t b0, uint32_t b1) {
    asm volatile(
        "mma.sync.aligned.m16n8k16.row.col.f32.f16.f16.f32 "
        "{%0,%1,%2,%3},{%4,%5,%6,%7},{%8,%9},{%0,%1,%2,%3};"
        : "+f"(c[0]), "+f"(c[1]), "+f"(c[2]), "+f"(c[3])
        : "r"(a[0]), "r"(a[1]), "r"(a[2]), "r"(a[3]), "r"(b0), "r"(b1));
}

__device__ __forceinline__ void stcs2(float* p, float2 v) {
    asm volatile("st.global.cs.v2.f32 [%0], {%1,%2};" :: "l"(p), "f"(v.x), "f"(v.y));
}

// ======================= Kernel 1: LayerNorm -> fp16 A =======================
__global__ __launch_bounds__(128) void ln_fp16_kernel(
    const float* __restrict__ z, const float* __restrict__ gamma,
    const float* __restrict__ beta)
{
    const int row = blockIdx.x;
    const int tid = threadIdx.x;
    const float4* zr = reinterpret_cast<const float4*>(z + (size_t)row * DZ);
    float4 a0 = zr[tid * 2], a1 = zr[tid * 2 + 1];
    float v[8] = {a0.x, a0.y, a0.z, a0.w, a1.x, a1.y, a1.z, a1.w};

    float s = 0.f, sq = 0.f;
#pragma unroll
    for (int i = 0; i < 8; i++) { s += v[i]; sq += v[i] * v[i]; }
#pragma unroll
    for (int o = 16; o > 0; o >>= 1) {
        s  += __shfl_xor_sync(0xFFFFFFFFu, s, o);
        sq += __shfl_xor_sync(0xFFFFFFFFu, sq, o);
    }
    __shared__ float ss[4], ssq[4], bc[2];
    const int wid = tid >> 5, lid = tid & 31;
    if (lid == 0) { ss[wid] = s; ssq[wid] = sq; }
    __syncthreads();
    if (tid == 0) {
        float ts = ss[0] + ss[1] + ss[2] + ss[3];
        float tq = ssq[0] + ssq[1] + ssq[2] + ssq[3];
        float mu = ts * (1.0f / DZ);
        float var = tq * (1.0f / DZ) - mu * mu;
        bc[0] = mu;
        bc[1] = rsqrtf(var + LN_EPS);
    }
    __syncthreads();
    const float mu = bc[0], inv = bc[1];

    const float4* gp = reinterpret_cast<const float4*>(gamma);
    const float4* bp = reinterpret_cast<const float4*>(beta);
    float4 g0 = gp[tid * 2], g1 = gp[tid * 2 + 1];
    float4 b0 = bp[tid * 2], b1 = bp[tid * 2 + 1];
    float gv[8] = {g0.x, g0.y, g0.z, g0.w, g1.x, g1.y, g1.z, g1.w};
    float bv[8] = {b0.x, b0.y, b0.z, b0.w, b1.x, b1.y, b1.z, b1.w};

    __half h[8];
#pragma unroll
    for (int i = 0; i < 8; i++)
        h[i] = __float2half((v[i] - mu) * inv * gv[i] + bv[i]);
    *reinterpret_cast<uint4*>(&g_A16[(size_t)row * DZ + tid * 8]) =
        *reinterpret_cast<uint4*>(h);
}

// ======================= Kernel 2: W -> fp16 =======================
__global__ __launch_bounds__(256) void w_fp16_kernel(const float* __restrict__ W)
{
    const size_t i0 = ((size_t)blockIdx.x * 256 + threadIdx.x) * 8;
    const float4* src = reinterpret_cast<const float4*>(W + i0);
    float4 a = src[0], b = src[1];
    __half h[8] = {__float2half(a.x), __float2half(a.y), __float2half(a.z), __float2half(a.w),
                   __float2half(b.x), __float2half(b.y), __float2half(b.z), __float2half(b.w)};
    *reinterpret_cast<uint4*>(&g_W16[i0]) = *reinterpret_cast<uint4*>(h);
}

// ======================= Kernel 3: fp16 HMMA GEMM + epilogue =======================
// CTA tile 256x128, 512 threads (16 warps), warp tile 64x32 (same as R3's proven shape),
// BK=32, 3-stage cp.async pipeline, ONE __syncthreads per chunk.
#define BM 256
#define BN 128
#define BK 32
#define NSTAGE 3
#define NCHUNK (DZ / BK)          // 32
#define GTHREADS 512

#define SA_STRIDE 40              // halves per A row (pad 8)
#define SB_STRIDE 136             // halves per B row (pad 8)
#define A_STAGE_BYTES (BM * SA_STRIDE * 2)   // 20480
#define B_STAGE_BYTES (BK * SB_STRIDE * 2)   // 8704
#define STAGE_BYTES (A_STAGE_BYTES + B_STAGE_BYTES)   // 29184
#define SMEM_TOTAL (NSTAGE * STAGE_BYTES)             // 87552

__global__ __launch_bounds__(GTHREADS, 1) void gemm_kernel(
    const float* __restrict__ bias, const float* __restrict__ scale,
    float* __restrict__ out)
{
    extern __shared__ char smem[];
    const uint32_t sbase = smem_u32(smem);
    const int tid = threadIdx.x;
    const int wid = tid >> 5;
    const int lane = tid & 31;
    const int bn = blockIdx.x;            // 0..31  (N tiles of 128) -- fastest for L2 reuse
    const int bm = blockIdx.y;            // 0..63  (M tiles of 256)
    const int wm = wid >> 2;              // 0..3  (64-row band)
    const int wn = wid & 3;               // 0..3  (32-col band)

    const __half* Abase = g_A16 + (size_t)bm * BM * DZ;
    const __half* Wbase = g_W16 + (size_t)bn * BN;

    const int arow = tid >> 2, ach = tid & 3;    // A: 256 rows x 4 x 16B (2 iters of 128)
    const int brow = tid >> 4, bch = tid & 15;   // B: 32 rows x 16 x 16B (1 iter)

    float acc[4][4][4];
#pragma unroll
    for (int i = 0; i < 4; i++)
#pragma unroll
        for (int j = 0; j < 4; j++)
#pragma unroll
            for (int q = 0; q < 4; q++) acc[i][j][q] = 0.f;

    auto load_stage = [&](int c, int st) {
        const int k0 = c * BK;
        const uint32_t sa = sbase + st * STAGE_BYTES;
        const uint32_t sb = sa + A_STAGE_BYTES;
#pragma unroll
        for (int i = 0; i < 2; i++) {
            const int r = arow + i * 128;
            cp_async16(sa + r * (SA_STRIDE * 2) + ach * 16,
                       Abase + (size_t)r * DZ + k0 + ach * 8);
        }
        cp_async16(sb + brow * (SB_STRIDE * 2) + bch * 16,
                   Wbase + (size_t)(k0 + brow) * DM + bch * 8);
        cp_commit();
    };

    load_stage(0, 0);
    load_stage(1, 1);

    for (int c = 0; c < NCHUNK; c++) {
        cp_wait<NSTAGE - 2>();
        __syncthreads();
        if (c + NSTAGE - 1 < NCHUNK) load_stage(c + NSTAGE - 1, (c + NSTAGE - 1) % NSTAGE);

        const int st = c % NSTAGE;
        const uint32_t sa = sbase + st * STAGE_BYTES;
        const uint32_t sb = sa + A_STAGE_BYTES;
#pragma unroll
        for (int kk = 0; kk < 2; kk++) {
            uint32_t af[4][4];
#pragma unroll
            for (int mt = 0; mt < 4; mt++) {
                const int r = wm * 64 + mt * 16 + (lane & 15);
                const int cb = (kk * 16 + (lane >> 4) * 8) * 2;
                ldsm_x4(af[mt][0], af[mt][1], af[mt][2], af[mt][3],
                        sa + r * (SA_STRIDE * 2) + cb);
            }
            uint32_t bf[2][4];
#pragma unroll
            for (int nt = 0; nt < 2; nt++) {
                const int r = kk * 16 + (lane & 15);
                const int cb = (wn * 32 + nt * 16 + (lane >> 4) * 8) * 2;
                ldsm_x4_t(bf[nt][0], bf[nt][1], bf[nt][2], bf[nt][3],
                          sb + r * (SB_STRIDE * 2) + cb);
            }
#pragma unroll
            for (int mt = 0; mt < 4; mt++) {
#pragma unroll
                for (int nt = 0; nt < 2; nt++) {
                    mma16816(acc[mt][nt * 2],     af[mt], bf[nt][0], bf[nt][1]);
                    mma16816(acc[mt][nt * 2 + 1], af[mt], bf[nt][2], bf[nt][3]);
                }
            }
        }
    }

    // ---- epilogue: (acc + bias) * scale -> tanh clamp, streaming fp32 stores ----
    const float sc = *scale;
    const int col0 = bn * BN + wn * 32 + (lane & 3) * 2;
    const int row0 = bm * BM + wm * 64 + (lane >> 2);
#pragma unroll
    for (int mt = 0; mt < 4; mt++) {
#pragma unroll
        for (int nt = 0; nt < 4; nt++) {
            const int col = col0 + nt * 8;
            const float b0 = __ldg(bias + col), b1 = __ldg(bias + col + 1);
#pragma unroll
            for (int half = 0; half < 2; half++) {
                const size_t r = (size_t)(row0 + mt * 16 + half * 8);
                float x0 = (acc[mt][nt][half * 2]     + b0) * sc;
                float x1 = (acc[mt][nt][half * 2 + 1] + b1) * sc;
                float2 o;
                o.x = tanhf(x0 * (1.0f / CLAMPV)) * CLAMPV;
                o.y = tanhf(x1 * (1.0f / CLAMPV)) * CLAMPV;
                stcs2(out + r * DM + col, o);
            }
        }
    }
}

// ======================= launch =======================
extern "C" void kernel_launch(void* const* d_in, const int* in_sizes, int n_in,
                              void* d_out, int out_size)
{
    (void)in_sizes; (void)n_in; (void)out_size;
    const float* z     = (const float*)d_in[0];
    const float* gamma = (const float*)d_in[1];
    const float* beta  = (const float*)d_in[2];
    const float* W     = (const float*)d_in[3];
    const float* bias  = (const float*)d_in[4];
    const float* scale = (const float*)d_in[5];
    float* out = (float*)d_out;

    ln_fp16_kernel<<<NROWS, 128>>>(z, gamma, beta);
    w_fp16_kernel<<<(DZ * DM) / (256 * 8), 256>>>(W);

    cudaFuncSetAttribute(gemm_kernel, cudaFuncAttributeMaxDynamicSharedMemorySize,
                         SMEM_TOTAL);
    dim3 gg(DM / BN, NROWS / BM);
    gemm_kernel<<<gg, GTHREADS, SMEM_TOTAL>>>(bias, scale, out);
}

// round 8
// speedup vs baseline: 1.2565x; 1.2448x over previous
#include <cuda_runtime.h>
#include <cuda_fp16.h>
#include <cstdint>

#define DZ 1024
#define DM 4096
#define NROWS 16384
#define LN_EPS 1e-5f
#define CLAMPV 3.0f

// -------- scratch (static device arrays; no allocation) --------
__device__ __align__(16) __half g_A16[NROWS * DZ];   // 32 MB, [M,K] row-major fp16
__device__ __align__(16) __half g_W16[DZ * DM];      //  8 MB, [K,N] row-major fp16

// ======================= small helpers =======================
__device__ __forceinline__ uint32_t smem_u32(const void* p) {
    uint32_t a;
    asm("{ .reg .u64 t; cvta.to.shared.u64 t, %1; cvt.u32.u64 %0, t; }"
        : "=r"(a) : "l"(p));
    return a;
}

__device__ __forceinline__ void cp_async16(uint32_t dst, const void* src) {
    asm volatile("cp.async.cg.shared.global [%0], [%1], 16;"
                 :: "r"(dst), "l"(src));
}
__device__ __forceinline__ void cp_commit() {
    asm volatile("cp.async.commit_group;");
}
template <int N>
__device__ __forceinline__ void cp_wait() {
    asm volatile("cp.async.wait_group %0;" :: "n"(N));
}

__device__ __forceinline__ void ldsm_x4(uint32_t& r0, uint32_t& r1, uint32_t& r2,
                                        uint32_t& r3, uint32_t addr) {
    asm volatile("ldmatrix.sync.aligned.m8n8.x4.shared.b16 {%0,%1,%2,%3}, [%4];"
                 : "=r"(r0), "=r"(r1), "=r"(r2), "=r"(r3) : "r"(addr));
}
__device__ __forceinline__ void ldsm_x4_t(uint32_t& r0, uint32_t& r1, uint32_t& r2,
                                          uint32_t& r3, uint32_t addr) {
    asm volatile("ldmatrix.sync.aligned.m8n8.x4.trans.shared.b16 {%0,%1,%2,%3}, [%4];"
                 : "=r"(r0), "=r"(r1), "=r"(r2), "=r"(r3) : "r"(addr));
}

__device__ __forceinline__ void mma16816(float* c, const uint32_t* a,
                                         uint32_t b0, uint32_t b1) {
    asm volatile(
        "mma.sync.aligned.m16n8k16.row.col.f32.f16.f16.f32 "
        "{%0,%1,%2,%3},{%4,%5,%6,%7},{%8,%9},{%0,%1,%2,%3};"
        : "+f"(c[0]), "+f"(c[1]), "+f"(c[2]), "+f"(c[3])
        : "r"(a[0]), "r"(a[1]), "r"(a[2]), "r"(a[3]), "r"(b0), "r"(b1));
}

__device__ __forceinline__ void stcs2(float* p, float2 v) {
    asm volatile("st.global.cs.v2.f32 [%0], {%1,%2};" :: "l"(p), "f"(v.x), "f"(v.y));
}

// ======================= Kernel 1: LayerNorm -> fp16 A =======================
__global__ __launch_bounds__(128) void ln_fp16_kernel(
    const float* __restrict__ z, const float* __restrict__ gamma,
    const float* __restrict__ beta)
{
    const int row = blockIdx.x;
    const int tid = threadIdx.x;
    const float4* zr = reinterpret_cast<const float4*>(z + (size_t)row * DZ);
    float4 a0 = zr[tid * 2], a1 = zr[tid * 2 + 1];
    float v[8] = {a0.x, a0.y, a0.z, a0.w, a1.x, a1.y, a1.z, a1.w};

    float s = 0.f, sq = 0.f;
#pragma unroll
    for (int i = 0; i < 8; i++) { s += v[i]; sq += v[i] * v[i]; }
#pragma unroll
    for (int o = 16; o > 0; o >>= 1) {
        s  += __shfl_xor_sync(0xFFFFFFFFu, s, o);
        sq += __shfl_xor_sync(0xFFFFFFFFu, sq, o);
    }
    __shared__ float ss[4], ssq[4], bc[2];
    const int wid = tid >> 5, lid = tid & 31;
    if (lid == 0) { ss[wid] = s; ssq[wid] = sq; }
    __syncthreads();
    if (tid == 0) {
        float ts = ss[0] + ss[1] + ss[2] + ss[3];
        float tq = ssq[0] + ssq[1] + ssq[2] + ssq[3];
        float mu = ts * (1.0f / DZ);
        float var = tq * (1.0f / DZ) - mu * mu;
        bc[0] = mu;
        bc[1] = rsqrtf(var + LN_EPS);
    }
    __syncthreads();
    const float mu = bc[0], inv = bc[1];

    const float4* gp = reinterpret_cast<const float4*>(gamma);
    const float4* bp = reinterpret_cast<const float4*>(beta);
    float4 g0 = gp[tid * 2], g1 = gp[tid * 2 + 1];
    float4 b0 = bp[tid * 2], b1 = bp[tid * 2 + 1];
    float gv[8] = {g0.x, g0.y, g0.z, g0.w, g1.x, g1.y, g1.z, g1.w};
    float bv[8] = {b0.x, b0.y, b0.z, b0.w, b1.x, b1.y, b1.z, b1.w};

    __half h[8];
#pragma unroll
    for (int i = 0; i < 8; i++)
        h[i] = __float2half((v[i] - mu) * inv * gv[i] + bv[i]);
    *reinterpret_cast<uint4*>(&g_A16[(size_t)row * DZ + tid * 8]) =
        *reinterpret_cast<uint4*>(h);
}

// ======================= Kernel 2: W -> fp16 =======================
__global__ __launch_bounds__(256) void w_fp16_kernel(const float* __restrict__ W)
{
    const size_t i0 = ((size_t)blockIdx.x * 256 + threadIdx.x) * 8;
    const float4* src = reinterpret_cast<const float4*>(W + i0);
    float4 a = src[0], b = src[1];
    __half h[8] = {__float2half(a.x), __float2half(a.y), __float2half(a.z), __float2half(a.w),
                   __float2half(b.x), __float2half(b.y), __float2half(b.z), __float2half(b.w)};
    *reinterpret_cast<uint4*>(&g_W16[i0]) = *reinterpret_cast<uint4*>(h);
}

// ======================= Kernel 3: fp16 HMMA GEMM + epilogue =======================
// R3 config: CTA tile 128x128, BK=32, 256 threads, warp tile 64x32, 2 CTAs/SM.
// Changes vs R3: NSTAGE 3->4, one __syncthreads per chunk, streaming stores.
#define BM 128
#define BN 128
#define BK 32
#define NSTAGE 4
#define NCHUNK (DZ / BK)          // 32
#define GTHREADS 256

#define SA_STRIDE 40              // halves per A row (pad 8)
#define SB_STRIDE 136             // halves per B row (pad 8)
#define A_STAGE_BYTES (BM * SA_STRIDE * 2)   // 10240
#define B_STAGE_BYTES (BK * SB_STRIDE * 2)   // 8704
#define STAGE_BYTES (A_STAGE_BYTES + B_STAGE_BYTES)   // 18944
#define SMEM_TOTAL (NSTAGE * STAGE_BYTES)             // 75776

__global__ __launch_bounds__(GTHREADS, 2) void gemm_kernel(
    const float* __restrict__ bias, const float* __restrict__ scale,
    float* __restrict__ out)
{
    extern __shared__ char smem[];
    const uint32_t sbase = smem_u32(smem);
    const int tid = threadIdx.x;
    const int wid = tid >> 5;
    const int lane = tid & 31;
    const int bm = blockIdx.x;            // 0..127
    const int bn = blockIdx.y;            // 0..31
    const int wm = wid >> 2;              // 0..1  (64-row band)
    const int wn = wid & 3;               // 0..3  (32-col band)

    const __half* Abase = g_A16 + (size_t)bm * BM * DZ;
    const __half* Wbase = g_W16 + (size_t)bn * BN;

    const int arow = tid >> 2, ach = tid & 3;          // A: 128 rows x 4 x 16B (x2)
    const int brow = tid >> 4, bch = tid & 15;         // B: 32 rows x 16 x 16B (x2)

    float acc[4][4][4];
#pragma unroll
    for (int i = 0; i < 4; i++)
#pragma unroll
        for (int j = 0; j < 4; j++)
#pragma unroll
            for (int q = 0; q < 4; q++) acc[i][j][q] = 0.f;

    auto load_stage = [&](int c, int st) {
        const int k0 = c * BK;
        const uint32_t sa = sbase + st * STAGE_BYTES;
        const uint32_t sb = sa + A_STAGE_BYTES;
#pragma unroll
        for (int i = 0; i < 2; i++) {
            const int r = arow + i * 64;
            cp_async16(sa + r * (SA_STRIDE * 2) + ach * 16,
                       Abase + (size_t)r * DZ + k0 + ach * 8);
        }
#pragma unroll
        for (int i = 0; i < 2; i++) {
            const int r = brow + i * 16;
            cp_async16(sb + r * (SB_STRIDE * 2) + bch * 16,
                       Wbase + (size_t)(k0 + r) * DM + bch * 8);
        }
        cp_commit();
    };

    load_stage(0, 0);
    load_stage(1, 1);
    load_stage(2, 2);

    for (int c = 0; c < NCHUNK; c++) {
        cp_wait<NSTAGE - 2>();
        __syncthreads();
        if (c + NSTAGE - 1 < NCHUNK) load_stage(c + NSTAGE - 1, (c + NSTAGE - 1) % NSTAGE);

        const int st = c % NSTAGE;
        const uint32_t sa = sbase + st * STAGE_BYTES;
        const uint32_t sb = sa + A_STAGE_BYTES;
#pragma unroll
        for (int kk = 0; kk < 2; kk++) {
            uint32_t af[4][4];
#pragma unroll
            for (int mt = 0; mt < 4; mt++) {
                const int r = wm * 64 + mt * 16 + (lane & 15);
                const int cb = (kk * 16 + (lane >> 4) * 8) * 2;
                ldsm_x4(af[mt][0], af[mt][1], af[mt][2], af[mt][3],
                        sa + r * (SA_STRIDE * 2) + cb);
            }
            uint32_t bf[2][4];
#pragma unroll
            for (int nt = 0; nt < 2; nt++) {
                const int r = kk * 16 + (lane & 15);
                const int cb = (wn * 32 + nt * 16 + (lane >> 4) * 8) * 2;
                ldsm_x4_t(bf[nt][0], bf[nt][1], bf[nt][2], bf[nt][3],
                          sb + r * (SB_STRIDE * 2) + cb);
            }
#pragma unroll
            for (int mt = 0; mt < 4; mt++) {
#pragma unroll
                for (int nt = 0; nt < 2; nt++) {
                    mma16816(acc[mt][nt * 2],     af[mt], bf[nt][0], bf[nt][1]);
                    mma16816(acc[mt][nt * 2 + 1], af[mt], bf[nt][2], bf[nt][3]);
                }
            }
        }
    }

    // ---- epilogue: (acc + bias) * scale -> tanh clamp, streaming fp32 stores ----
    const float sc = *scale;
    const int col0 = bn * BN + wn * 32 + (lane & 3) * 2;
    const int row0 = bm * BM + wm * 64 + (lane >> 2);
#pragma unroll
    for (int mt = 0; mt < 4; mt++) {
#pragma unroll
        for (int nt = 0; nt < 4; nt++) {
            const int col = col0 + nt * 8;
            const float b0 = __ldg(bias + col), b1 = __ldg(bias + col + 1);
#pragma unroll
            for (int half = 0; half < 2; half++) {
                const size_t r = (size_t)(row0 + mt * 16 + half * 8);
                float x0 = (acc[mt][nt][half * 2]     + b0) * sc;
                float x1 = (acc[mt][nt][half * 2 + 1] + b1) * sc;
                float2 o;
                o.x = tanhf(x0 * (1.0f / CLAMPV)) * CLAMPV;
                o.y = tanhf(x1 * (1.0f / CLAMPV)) * CLAMPV;
                stcs2(out + r * DM + col, o);
            }
        }
    }
}

// ======================= launch =======================
extern "C" void kernel_launch(void* const* d_in, const int* in_sizes, int n_in,
                              void* d_out, int out_size)
{
    (void)in_sizes; (void)n_in; (void)out_size;
    const float* z     = (const float*)d_in[0];
    const float* gamma = (const float*)d_in[1];
    const float* beta  = (const float*)d_in[2];
    const float* W     = (const float*)d_in[3];
    const float* bias  = (const float*)d_in[4];
    const float* scale = (const float*)d_in[5];
    float* out = (float*)d_out;

    ln_fp16_kernel<<<NROWS, 128>>>(z, gamma, beta);
    w_fp16_kernel<<<(DZ * DM) / (256 * 8), 256>>>(W);

    cudaFuncSetAttribute(gemm_kernel, cudaFuncAttributeMaxDynamicSharedMemorySize,
                         SMEM_TOTAL);
    dim3 gg(NROWS / BM, DM / BN);
    gemm_kernel<<<gg, GTHREADS, SMEM_TOTAL>>>(bias, scale, out);
}

// round 14
// speedup vs baseline: 1.2808x; 1.0193x over previous
#include <cuda_runtime.h>
#include <cuda_fp16.h>
#include <cstdint>

#define DZ 1024
#define DM 4096
#define NROWS 16384
#define LN_EPS 1e-5f
#define CLAMPV 3.0f

// -------- scratch (static device arrays; no allocation) --------
__device__ __align__(16) __half g_A16[NROWS * DZ];   // 32 MB, [M,K] row-major fp16
__device__ __align__(16) __half g_W16[DZ * DM];      //  8 MB, [K,N] row-major fp16

// ======================= small helpers =======================
__device__ __forceinline__ uint32_t smem_u32(const void* p) {
    uint32_t a;
    asm("{ .reg .u64 t; cvta.to.shared.u64 t, %1; cvt.u32.u64 %0, t; }"
        : "=r"(a) : "l"(p));
    return a;
}

__device__ __forceinline__ void cp_async16(uint32_t dst, const void* src) {
    asm volatile("cp.async.cg.shared.global [%0], [%1], 16;"
                 :: "r"(dst), "l"(src));
}
__device__ __forceinline__ void cp_commit() {
    asm volatile("cp.async.commit_group;");
}
template <int N>
__device__ __forceinline__ void cp_wait() {
    asm volatile("cp.async.wait_group %0;" :: "n"(N));
}

__device__ __forceinline__ void ldsm_x4(uint32_t& r0, uint32_t& r1, uint32_t& r2,
                                        uint32_t& r3, uint32_t addr) {
    asm volatile("ldmatrix.sync.aligned.m8n8.x4.shared.b16 {%0,%1,%2,%3}, [%4];"
                 : "=r"(r0), "=r"(r1), "=r"(r2), "=r"(r3) : "r"(addr));
}
__device__ __forceinline__ void ldsm_x4_t(uint32_t& r0, uint32_t& r1, uint32_t& r2,
                                          uint32_t& r3, uint32_t addr) {
    asm volatile("ldmatrix.sync.aligned.m8n8.x4.trans.shared.b16 {%0,%1,%2,%3}, [%4];"
                 : "=r"(r0), "=r"(r1), "=r"(r2), "=r"(r3) : "r"(addr));
}

__device__ __forceinline__ void mma16816(float* c, const uint32_t* a,
                                         uint32_t b0, uint32_t b1) {
    asm volatile(
        "mma.sync.aligned.m16n8k16.row.col.f32.f16.f16.f32 "
        "{%0,%1,%2,%3},{%4,%5,%6,%7},{%8,%9},{%0,%1,%2,%3};"
        : "+f"(c[0]), "+f"(c[1]), "+f"(c[2]), "+f"(c[3])
        : "r"(a[0]), "r"(a[1]), "r"(a[2]), "r"(a[3]), "r"(b0), "r"(b1));
}

__device__ __forceinline__ void stcs2(float* p, float2 v) {
    asm volatile("st.global.cs.v2.f32 [%0], {%1,%2};" :: "l"(p), "f"(v.x), "f"(v.y));
}

// branchless fast tanh: (1-e^{-2|y|})/(1+e^{-2|y|}) with sign restore; NaN-free for finite y
__device__ __forceinline__ float fast_tanh(float y) {
    float ay = fabsf(y);
    float e = __expf(-2.0f * ay);
    float t = __fdividef(1.0f - e, 1.0f + e);
    return copysignf(t, y);
}

// ======================= Kernel 1: LayerNorm -> fp16 A =======================
__global__ __launch_bounds__(128) void ln_fp16_kernel(
    const float* __restrict__ z, const float* __restrict__ gamma,
    const float* __restrict__ beta)
{
    const int row = blockIdx.x;
    const int tid = threadIdx.x;
    const float4* zr = reinterpret_cast<const float4*>(z + (size_t)row * DZ);
    float4 a0 = zr[tid * 2], a1 = zr[tid * 2 + 1];
    float v[8] = {a0.x, a0.y, a0.z, a0.w, a1.x, a1.y, a1.z, a1.w};

    float s = 0.f, sq = 0.f;
#pragma unroll
    for (int i = 0; i < 8; i++) { s += v[i]; sq += v[i] * v[i]; }
#pragma unroll
    for (int o = 16; o > 0; o >>= 1) {
        s  += __shfl_xor_sync(0xFFFFFFFFu, s, o);
        sq += __shfl_xor_sync(0xFFFFFFFFu, sq, o);
    }
    __shared__ float ss[4], ssq[4], bc[2];
    const int wid = tid >> 5, lid = tid & 31;
    if (lid == 0) { ss[wid] = s; ssq[wid] = sq; }
    __syncthreads();
    if (tid == 0) {
        float ts = ss[0] + ss[1] + ss[2] + ss[3];
        float tq = ssq[0] + ssq[1] + ssq[2] + ssq[3];
        float mu = ts * (1.0f / DZ);
        float var = tq * (1.0f / DZ) - mu * mu;
        bc[0] = mu;
        bc[1] = rsqrtf(var + LN_EPS);
    }
    __syncthreads();
    const float mu = bc[0], inv = bc[1];

    const float4* gp = reinterpret_cast<const float4*>(gamma);
    const float4* bp = reinterpret_cast<const float4*>(beta);
    float4 g0 = gp[tid * 2], g1 = gp[tid * 2 + 1];
    float4 b0 = bp[tid * 2], b1 = bp[tid * 2 + 1];
    float gv[8] = {g0.x, g0.y, g0.z, g0.w, g1.x, g1.y, g1.z, g1.w};
    float bv[8] = {b0.x, b0.y, b0.z, b0.w, b1.x, b1.y, b1.z, b1.w};

    __half h[8];
#pragma unroll
    for (int i = 0; i < 8; i++)
        h[i] = __float2half((v[i] - mu) * inv * gv[i] + bv[i]);
    *reinterpret_cast<uint4*>(&g_A16[(size_t)row * DZ + tid * 8]) =
        *reinterpret_cast<uint4*>(h);
}

// ======================= Kernel 2: W -> fp16 =======================
__global__ __launch_bounds__(256) void w_fp16_kernel(const float* __restrict__ W)
{
    const size_t i0 = ((size_t)blockIdx.x * 256 + threadIdx.x) * 8;
    const float4* src = reinterpret_cast<const float4*>(W + i0);
    float4 a = src[0], b = src[1];
    __half h[8] = {__float2half(a.x), __float2half(a.y), __float2half(a.z), __float2half(a.w),
                   __float2half(b.x), __float2half(b.y), __float2half(b.z), __float2half(b.w)};
    *reinterpret_cast<uint4*>(&g_W16[i0]) = *reinterpret_cast<uint4*>(h);
}

// ======================= Kernel 3: fp16 HMMA GEMM + epilogue =======================
// CTA tile 128x128, BK=64, 256 threads, warp tile 64x32, 2 CTAs/SM, NSTAGE=3.
#define BM 128
#define BN 128
#define BK 64
#define NSTAGE 3
#define NCHUNK (DZ / BK)          // 16
#define GTHREADS 256

#define SA_STRIDE 72              // halves per A row (64 + pad 8)
#define SB_STRIDE 136             // halves per B row (128 + pad 8)
#define A_STAGE_BYTES (BM * SA_STRIDE * 2)   // 18432
#define B_STAGE_BYTES (BK * SB_STRIDE * 2)   // 17408
#define STAGE_BYTES (A_STAGE_BYTES + B_STAGE_BYTES)   // 35840
#define SMEM_TOTAL (NSTAGE * STAGE_BYTES)             // 107520

__global__ __launch_bounds__(GTHREADS, 2) void gemm_kernel(
    const float* __restrict__ bias, const float* __restrict__ scale,
    float* __restrict__ out)
{
    extern __shared__ char smem[];
    const uint32_t sbase = smem_u32(smem);
    const int tid = threadIdx.x;
    const int wid = tid >> 5;
    const int lane = tid & 31;
    const int bm = blockIdx.x;            // 0..127
    const int bn = blockIdx.y;            // 0..31
    const int wm = wid >> 2;              // 0..1  (64-row band)
    const int wn = wid & 3;               // 0..3  (32-col band)

    const __half* Abase = g_A16 + (size_t)bm * BM * DZ;
    const __half* Wbase = g_W16 + (size_t)bn * BN;

    // A: 128 rows x 8 x 16B segments (row = 64 halves = 128B) = 1024 = 256 thr x 4
    const int arow = tid >> 3, ach = tid & 7;
    // B: 64 rows x 16 x 16B segments (row = 128 halves = 256B) = 1024 = 256 thr x 4
    const int brow = tid >> 4, bch = tid & 15;

    float acc[4][4][4];
#pragma unroll
    for (int i = 0; i < 4; i++)
#pragma unroll
        for (int j = 0; j < 4; j++)
#pragma unroll
            for (int q = 0; q < 4; q++) acc[i][j][q] = 0.f;

    auto load_stage = [&](int c, int st) {
        const int k0 = c * BK;
        const uint32_t sa = sbase + st * STAGE_BYTES;
        const uint32_t sb = sa + A_STAGE_BYTES;
#pragma unroll
        for (int i = 0; i < 4; i++) {
            const int r = arow + i * 32;
            cp_async16(sa + r * (SA_STRIDE * 2) + ach * 16,
                       Abase + (size_t)r * DZ + k0 + ach * 8);
        }
#pragma unroll
        for (int i = 0; i < 4; i++) {
            const int r = brow + i * 16;
            cp_async16(sb + r * (SB_STRIDE * 2) + bch * 16,
                       Wbase + (size_t)(k0 + r) * DM + bch * 8);
        }
        cp_commit();
    };

    load_stage(0, 0);
    load_stage(1, 1);

    for (int c = 0; c < NCHUNK; c++) {
        cp_wait<NSTAGE - 2>();
        __syncthreads();
        if (c + NSTAGE - 1 < NCHUNK) load_stage(c + NSTAGE - 1, (c + NSTAGE - 1) % NSTAGE);

        const int st = c % NSTAGE;
        const uint32_t sa = sbase + st * STAGE_BYTES;
        const uint32_t sb = sa + A_STAGE_BYTES;
#pragma unroll
        for (int kk = 0; kk < 4; kk++) {
            uint32_t af[4][4];
#pragma unroll
            for (int mt = 0; mt < 4; mt++) {
                const int r = wm * 64 + mt * 16 + (lane & 15);
                const int cb = (kk * 16 + (lane >> 4) * 8) * 2;
                ldsm_x4(af[mt][0], af[mt][1], af[mt][2], af[mt][3],
                        sa + r * (SA_STRIDE * 2) + cb);
            }
            uint32_t bf[2][4];
#pragma unroll
            for (int nt = 0; nt < 2; nt++) {
                const int r = kk * 16 + (lane & 15);
                const int cb = (wn * 32 + nt * 16 + (lane >> 4) * 8) * 2;
                ldsm_x4_t(bf[nt][0], bf[nt][1], bf[nt][2], bf[nt][3],
                          sb + r * (SB_STRIDE * 2) + cb);
            }
#pragma unroll
            for (int mt = 0; mt < 4; mt++) {
#pragma unroll
                for (int nt = 0; nt < 2; nt++) {
                    mma16816(acc[mt][nt * 2],     af[mt], bf[nt][0], bf[nt][1]);
                    mma16816(acc[mt][nt * 2 + 1], af[mt], bf[nt][2], bf[nt][3]);
                }
            }
        }
    }

    // ---- epilogue: (acc + bias) * scale -> fast tanh clamp, streaming fp32 stores ----
    const float sc = *scale;
    const int col0 = bn * BN + wn * 32 + (lane & 3) * 2;
    const int row0 = bm * BM + wm * 64 + (lane >> 2);
#pragma unroll
    for (int mt = 0; mt < 4; mt++) {
#pragma unroll
        for (int nt = 0; nt < 4; nt++) {
            const int col = col0 + nt * 8;
            const float b0 = __ldg(bias + col), b1 = __ldg(bias + col + 1);
#pragma unroll
            for (int half = 0; half < 2; half++) {
                const size_t r = (size_t)(row0 + mt * 16 + half * 8);
                float x0 = (acc[mt][nt][half * 2]     + b0) * sc;
                float x1 = (acc[mt][nt][half * 2 + 1] + b1) * sc;
                float2 o;
                o.x = fast_tanh(x0 * (1.0f / CLAMPV)) * CLAMPV;
                o.y = fast_tanh(x1 * (1.0f / CLAMPV)) * CLAMPV;
                stcs2(out + r * DM + col, o);
            }
        }
    }
}

// ======================= launch =======================
extern "C" void kernel_launch(void* const* d_in, const int* in_sizes, int n_in,
                              void* d_out, int out_size)
{
    (void)in_sizes; (void)n_in; (void)out_size;
    const float* z     = (const float*)d_in[0];
    const float* gamma = (const float*)d_in[1];
    const float* beta  = (const float*)d_in[2];
    const float* W     = (const float*)d_in[3];
    const float* bias  = (const float*)d_in[4];
    const float* scale = (const float*)d_in[5];
    float* out = (float*)d_out;

    ln_fp16_kernel<<<NROWS, 128>>>(z, gamma, beta);
    w_fp16_kernel<<<(DZ * DM) / (256 * 8), 256>>>(W);

    cudaFuncSetAttribute(gemm_kernel, cudaFuncAttributeMaxDynamicSharedMemorySize,
                         SMEM_TOTAL);
    dim3 gg(NROWS / BM, DM / BN);
    gemm_kernel<<<gg, GTHREADS, SMEM_TOTAL>>>(bias, scale, out);
}